// round 1
// baseline (speedup 1.0000x reference)
#include <cuda_runtime.h>

#define Bn 4
#define Ln 2048
#define Dn 1024
#define Hn 16
#define DKn 64
#define BLn (Bn*Ln)   // 8192
#define BHn (Bn*Hn)   // 64

// head-major scratch [B,H,L,64]
__device__ float g_qh[BHn*Ln*DKn];
__device__ float g_kh[BHn*Ln*DKn];
__device__ float g_vh[BHn*Ln*DKn];
__device__ float g_oh[BHn*Ln*DKn];

// ---------------------------------------------------------------------------
// QKV projection: C[8192,1024] = A @ W + b, scattered to head layout.
// 128x128 block tile, BK=16, 256 threads, 8x8 micro-tile.
// ---------------------------------------------------------------------------
__global__ __launch_bounds__(256) void proj_qkv_kernel(
    const float* __restrict__ q, const float* __restrict__ k, const float* __restrict__ v,
    const float* __restrict__ Wq, const float* __restrict__ Wk, const float* __restrict__ Wv,
    const float* __restrict__ bq, const float* __restrict__ bk, const float* __restrict__ bv)
{
    const int z = blockIdx.z;
    const float* A    = (z == 0) ? q  : (z == 1) ? k  : v;
    const float* W    = (z == 0) ? Wq : (z == 1) ? Wk : Wv;
    const float* bias = (z == 0) ? bq : (z == 1) ? bk : bv;
    float* dst        = (z == 0) ? g_qh : (z == 1) ? g_kh : g_vh;

    __shared__ float As[16][132];
    __shared__ float Bs[16][132];

    const int tid = threadIdx.x;
    const int tx = tid & 15, ty = tid >> 4;
    const int m0 = blockIdx.y * 128;
    const int n0 = blockIdx.x * 128;

    float acc[8][8];
#pragma unroll
    for (int i = 0; i < 8; i++)
#pragma unroll
        for (int j = 0; j < 8; j++) acc[i][j] = 0.f;

    for (int k0 = 0; k0 < 1024; k0 += 16) {
#pragma unroll
        for (int i = 0; i < 2; i++) {             // A tile 128x16 (transposed store)
            int id = tid + i * 256;
            int ar = id >> 2, ac4 = id & 3;
            float4 va = *(const float4*)&A[(size_t)(m0 + ar) * 1024 + k0 + ac4 * 4];
            As[ac4 * 4 + 0][ar] = va.x;
            As[ac4 * 4 + 1][ar] = va.y;
            As[ac4 * 4 + 2][ar] = va.z;
            As[ac4 * 4 + 3][ar] = va.w;
        }
#pragma unroll
        for (int i = 0; i < 2; i++) {             // B tile 16x128
            int id = tid + i * 256;
            int br = id >> 5, bc4 = id & 31;
            *(float4*)&Bs[br][bc4 * 4] =
                *(const float4*)&W[(size_t)(k0 + br) * 1024 + n0 + bc4 * 4];
        }
        __syncthreads();
#pragma unroll
        for (int kk = 0; kk < 16; kk++) {
            float a[8], bb[8];
            *(float4*)&a[0]  = *(const float4*)&As[kk][ty * 8];
            *(float4*)&a[4]  = *(const float4*)&As[kk][ty * 8 + 4];
            *(float4*)&bb[0] = *(const float4*)&Bs[kk][tx * 8];
            *(float4*)&bb[4] = *(const float4*)&Bs[kk][tx * 8 + 4];
#pragma unroll
            for (int i = 0; i < 8; i++)
#pragma unroll
                for (int j = 0; j < 8; j++) acc[i][j] += a[i] * bb[j];
        }
        __syncthreads();
    }
#pragma unroll
    for (int i = 0; i < 8; i++) {
        int gm = m0 + ty * 8 + i;
        int bb_ = gm >> 11;          // /2048
        int l   = gm & 2047;
#pragma unroll
        for (int j = 0; j < 8; j++) {
            int gn = n0 + tx * 8 + j;
            int h = gn >> 6, d = gn & 63;
            dst[(size_t)((bb_ * Hn + h) * Ln + l) * 64 + d] = acc[i][j] + bias[gn];
        }
    }
}

// ---------------------------------------------------------------------------
// Output projection: out[8192,1024] = gather(g_oh) @ Wo + bo
// ---------------------------------------------------------------------------
__global__ __launch_bounds__(256) void out_proj_kernel(
    const float* __restrict__ Wo, const float* __restrict__ bo, float* __restrict__ out)
{
    __shared__ float As[16][132];
    __shared__ float Bs[16][132];

    const int tid = threadIdx.x;
    const int tx = tid & 15, ty = tid >> 4;
    const int m0 = blockIdx.y * 128;
    const int n0 = blockIdx.x * 128;

    float acc[8][8];
#pragma unroll
    for (int i = 0; i < 8; i++)
#pragma unroll
        for (int j = 0; j < 8; j++) acc[i][j] = 0.f;

    for (int k0 = 0; k0 < 1024; k0 += 16) {
#pragma unroll
        for (int i = 0; i < 2; i++) {
            int id = tid + i * 256;
            int ar = id >> 2, ac4 = id & 3;
            int gr = m0 + ar;
            int bb_ = gr >> 11, l = gr & 2047;
            int kk = k0 + ac4 * 4;
            int h = kk >> 6, dv = kk & 63;     // 4-span never crosses a 64 boundary
            float4 va = *(const float4*)&g_oh[(size_t)((bb_ * Hn + h) * Ln + l) * 64 + dv];
            As[ac4 * 4 + 0][ar] = va.x;
            As[ac4 * 4 + 1][ar] = va.y;
            As[ac4 * 4 + 2][ar] = va.z;
            As[ac4 * 4 + 3][ar] = va.w;
        }
#pragma unroll
        for (int i = 0; i < 2; i++) {
            int id = tid + i * 256;
            int br = id >> 5, bc4 = id & 31;
            *(float4*)&Bs[br][bc4 * 4] =
                *(const float4*)&Wo[(size_t)(k0 + br) * 1024 + n0 + bc4 * 4];
        }
        __syncthreads();
#pragma unroll
        for (int kk = 0; kk < 16; kk++) {
            float a[8], bb[8];
            *(float4*)&a[0]  = *(const float4*)&As[kk][ty * 8];
            *(float4*)&a[4]  = *(const float4*)&As[kk][ty * 8 + 4];
            *(float4*)&bb[0] = *(const float4*)&Bs[kk][tx * 8];
            *(float4*)&bb[4] = *(const float4*)&Bs[kk][tx * 8 + 4];
#pragma unroll
            for (int i = 0; i < 8; i++)
#pragma unroll
                for (int j = 0; j < 8; j++) acc[i][j] += a[i] * bb[j];
        }
        __syncthreads();
    }
#pragma unroll
    for (int i = 0; i < 8; i++) {
        int gm = m0 + ty * 8 + i;
#pragma unroll
        for (int j = 0; j < 8; j++) {
            int gn = n0 + tx * 8 + j;
            out[(size_t)gm * 1024 + gn] = acc[i][j] + bo[gn];
        }
    }
}

// ---------------------------------------------------------------------------
// Fused attention: one CTA per (b, h, 16-row q tile).
// Scores -> smem S[16][2048] -> masked softmax -> write attn -> P@V -> g_oh.
// Dynamic smem layout (floats):
//   S  [16][2052]                : 32832
//   Qs [64][16]                  : 1024
//   KV [16][512] | [128][64]     : 8192
//   Pd [4][16][64]               : 4096
// total 46144 floats = 184576 B
// ---------------------------------------------------------------------------
#define QT 16
#define SPAD 2052
#define ATTN_SMEM_FLOATS (16*SPAD + 64*16 + 16*512 + 4*16*64)

__global__ __launch_bounds__(256) void attn_kernel(
    const int* __restrict__ mask, float* __restrict__ attn_out)
{
    extern __shared__ float sm[];
    float* S  = sm;                       // [16][SPAD]
    float* Qs = sm + 16 * SPAD;           // [64][16]
    float* KV = Qs + 64 * 16;             // [16][512] / [128][64]
    float* Pd = KV + 16 * 512;            // [4][16][64]

    const int tid = threadIdx.x;
    const int q0 = blockIdx.x * QT;
    const int h  = blockIdx.y;
    const int b  = blockIdx.z;
    const int bh = b * Hn + h;
    const float* Qh = g_qh + (size_t)bh * Ln * 64;
    const float* Kh = g_kh + (size_t)bh * Ln * 64;
    const float* Vh = g_vh + (size_t)bh * Ln * 64;

    // ---- load Q tile transposed: Qs[d][r] ----
    {
        int r = tid >> 4, d4 = tid & 15;
        float4 vq = *(const float4*)&Qh[(size_t)(q0 + r) * 64 + d4 * 4];
        Qs[(d4 * 4 + 0) * 16 + r] = vq.x;
        Qs[(d4 * 4 + 1) * 16 + r] = vq.y;
        Qs[(d4 * 4 + 2) * 16 + r] = vq.z;
        Qs[(d4 * 4 + 3) * 16 + r] = vq.w;
    }
    __syncthreads();

    // ---- scores: S = Q @ K^T * (1/8) ----
    {
        const int tr = tid >> 6;      // 0..3 (row group of 4)
        const int tc = tid & 63;      // 0..63 (col group of 8)
        for (int jt = 0; jt < 4; jt++) {
            const int j0 = jt * 512;
            float acc[4][8];
#pragma unroll
            for (int i = 0; i < 4; i++)
#pragma unroll
                for (int j = 0; j < 8; j++) acc[i][j] = 0.f;

            for (int kc = 0; kc < 4; kc++) {
#pragma unroll
                for (int i = 0; i < 8; i++) {      // load Ks[16][512] transposed
                    int id = tid + i * 256;        // float4 id 0..2047
                    int j  = id >> 2;              // 0..511
                    int d4 = id & 3;               // 0..3
                    float4 vk = *(const float4*)&Kh[(size_t)(j0 + j) * 64 + kc * 16 + d4 * 4];
                    KV[(d4 * 4 + 0) * 512 + j] = vk.x;
                    KV[(d4 * 4 + 1) * 512 + j] = vk.y;
                    KV[(d4 * 4 + 2) * 512 + j] = vk.z;
                    KV[(d4 * 4 + 3) * 512 + j] = vk.w;
                }
                __syncthreads();
#pragma unroll
                for (int kk = 0; kk < 16; kk++) {
                    int d = kc * 16 + kk;
                    float a[4], bb[8];
                    *(float4*)&a[0]  = *(const float4*)&Qs[d * 16 + tr * 4];
                    *(float4*)&bb[0] = *(const float4*)&KV[kk * 512 + tc * 8];
                    *(float4*)&bb[4] = *(const float4*)&KV[kk * 512 + tc * 8 + 4];
#pragma unroll
                    for (int i = 0; i < 4; i++)
#pragma unroll
                        for (int j = 0; j < 8; j++) acc[i][j] += a[i] * bb[j];
                }
                __syncthreads();
            }
#pragma unroll
            for (int i = 0; i < 4; i++)
#pragma unroll
                for (int j = 0; j < 8; j++)
                    S[(tr * 4 + i) * SPAD + j0 + tc * 8 + j] = acc[i][j] * 0.125f;
        }
    }
    __syncthreads();

    // ---- masked softmax per row + write attn ----
    {
        const int warp = tid >> 5, lane = tid & 31;
        for (int rr = 0; rr < 2; rr++) {
            const int r = warp * 2 + rr;
            float* Sr = S + r * SPAD;
            const int* mr = mask + (size_t)(b * Ln + q0 + r) * Ln;
            float mx = -1e30f;
            for (int j = lane; j < Ln; j += 32) mx = fmaxf(mx, Sr[j]);
#pragma unroll
            for (int o = 16; o; o >>= 1) mx = fmaxf(mx, __shfl_xor_sync(~0u, mx, o));
            float sum = 0.f;
            for (int j = lane; j < Ln; j += 32) {
                float p = (mr[j] != 0) ? __expf(Sr[j] - mx) : 0.f;
                Sr[j] = p;
                sum += p;
            }
#pragma unroll
            for (int o = 16; o; o >>= 1) sum += __shfl_xor_sync(~0u, sum, o);
            float inv = 1.f / sum;
            float* arow = attn_out + ((size_t)bh * Ln + q0 + r) * Ln;
            for (int j = lane; j < Ln; j += 32) {
                float p = Sr[j] * inv;
                Sr[j] = p;
                arow[j] = p;
            }
        }
    }
    __syncthreads();

    // ---- O = P @ V ----
    {
        const int g  = tid >> 6;          // 0..3 j-split
        const int rr = (tid >> 4) & 3;    // 0..3 row group
        const int cc = tid & 15;          // 0..15 col group of 4
        float acc[4][4];
#pragma unroll
        for (int i = 0; i < 4; i++)
#pragma unroll
            for (int j = 0; j < 4; j++) acc[i][j] = 0.f;

        for (int jc = 0; jc < 16; jc++) {
#pragma unroll
            for (int i = 0; i < 8; i++) {      // load Vs[128][64] straight copy
                int id = tid + i * 256;        // float4 id
                *(float4*)&KV[id * 4] =
                    *(const float4*)&Vh[(size_t)(jc * 128) * 64 + id * 4];
            }
            __syncthreads();
#pragma unroll
            for (int jj = 0; jj < 32; jj++) {
                int jl = g * 32 + jj;
                int sj = jc * 128 + jl;
                float4 v4 = *(const float4*)&KV[jl * 64 + cc * 4];
#pragma unroll
                for (int i = 0; i < 4; i++) {
                    float s = S[(rr * 4 + i) * SPAD + sj];
                    acc[i][0] += s * v4.x;
                    acc[i][1] += s * v4.y;
                    acc[i][2] += s * v4.z;
                    acc[i][3] += s * v4.w;
                }
            }
            __syncthreads();
        }
#pragma unroll
        for (int i = 0; i < 4; i++) {
            float4 w = make_float4(acc[i][0], acc[i][1], acc[i][2], acc[i][3]);
            *(float4*)&Pd[(g * 16 + rr * 4 + i) * 64 + cc * 4] = w;
        }
        __syncthreads();
#pragma unroll
        for (int t = 0; t < 4; t++) {
            int o = tid + t * 256;           // 0..1023
            int r = o >> 6, c = o & 63;
            float s = Pd[(0 * 16 + r) * 64 + c] + Pd[(1 * 16 + r) * 64 + c]
                    + Pd[(2 * 16 + r) * 64 + c] + Pd[(3 * 16 + r) * 64 + c];
            g_oh[((size_t)bh * Ln + q0 + r) * 64 + c] = s;
        }
    }
}

// ---------------------------------------------------------------------------
extern "C" void kernel_launch(void* const* d_in, const int* in_sizes, int n_in,
                              void* d_out, int out_size)
{
    const float* q    = (const float*)d_in[0];
    const float* k    = (const float*)d_in[1];
    const float* v    = (const float*)d_in[2];
    const int*   mask = (const int*)d_in[3];
    const float* Wq   = (const float*)d_in[4];
    const float* bq   = (const float*)d_in[5];
    const float* Wk   = (const float*)d_in[6];
    const float* bk   = (const float*)d_in[7];
    const float* Wv   = (const float*)d_in[8];
    const float* bv   = (const float*)d_in[9];
    const float* Wo   = (const float*)d_in[10];
    const float* bo   = (const float*)d_in[11];

    float* out  = (float*)d_out;                    // [B,L,D]
    float* attn = out + (size_t)BLn * Dn;           // [B,H,L,L]

    // 1) QKV projections into head-major scratch
    proj_qkv_kernel<<<dim3(8, 64, 3), 256>>>(q, k, v, Wq, Wk, Wv, bq, bk, bv);

    // 2) fused attention (scores + masked softmax + attn write + P@V)
    int smem_bytes = ATTN_SMEM_FLOATS * (int)sizeof(float);
    cudaFuncSetAttribute(attn_kernel, cudaFuncAttributeMaxDynamicSharedMemorySize, smem_bytes);
    attn_kernel<<<dim3(Ln / QT, Hn, Bn), 256, smem_bytes>>>(mask, attn);

    // 3) output projection
    out_proj_kernel<<<dim3(8, 64), 256>>>(Wo, bo, out);
}

// round 2
// speedup vs baseline: 2.8630x; 2.8630x over previous
#include <cuda_runtime.h>

#define Bn 4
#define Ln 2048
#define Dn 1024
#define Hn 16
#define BLn (Bn*Ln)   // 8192
#define BHn (Bn*Hn)   // 64

// head-major scratch [B,H,L,64]
__device__ float g_qh[BHn*Ln*64];
__device__ float g_kh[BHn*Ln*64];
__device__ float g_vh[BHn*Ln*64];
__device__ float g_oh[BHn*Ln*64];

// ---------------------------------------------------------------------------
// tf32 mma helpers
// ---------------------------------------------------------------------------
__device__ __forceinline__ unsigned f2tf(float x) {
    unsigned r;
    asm("cvt.rna.tf32.f32 %0, %1;" : "=r"(r) : "f"(x));
    return r;
}

__device__ __forceinline__ void mma8(float d[4], const unsigned a[4], const unsigned b[2]) {
    asm volatile(
        "mma.sync.aligned.m16n8k8.row.col.f32.tf32.tf32.f32 "
        "{%0,%1,%2,%3}, {%4,%5,%6,%7}, {%8,%9}, {%0,%1,%2,%3};"
        : "+f"(d[0]), "+f"(d[1]), "+f"(d[2]), "+f"(d[3])
        : "r"(a[0]), "r"(a[1]), "r"(a[2]), "r"(a[3]), "r"(b[0]), "r"(b[1]));
}

// ---------------------------------------------------------------------------
// Projection GEMM (tf32 mma): C[8192,1024] = A @ W + b  -> head layout
// Block 128x128, k-chunk 32. 8 warps (4m x 2n), warp tile 32x64.
// ---------------------------------------------------------------------------
__global__ __launch_bounds__(256) void proj_qkv_kernel(
    const float* __restrict__ q, const float* __restrict__ k, const float* __restrict__ v,
    const float* __restrict__ Wq, const float* __restrict__ Wk, const float* __restrict__ Wv,
    const float* __restrict__ bq, const float* __restrict__ bk, const float* __restrict__ bv)
{
    const int z = blockIdx.z;
    const float* A    = (z == 0) ? q  : (z == 1) ? k  : v;
    const float* W    = (z == 0) ? Wq : (z == 1) ? Wk : Wv;
    const float* bias = (z == 0) ? bq : (z == 1) ? bk : bv;
    float* dst        = (z == 0) ? g_qh : (z == 1) ? g_kh : g_vh;

    __shared__ float As[128][40];   // [m][k]
    __shared__ float Ws[32][136];   // [k][n]

    const int tid  = threadIdx.x;
    const int lane = tid & 31;
    const int warp = tid >> 5;
    const int g    = lane >> 2;
    const int tig  = lane & 3;
    const int wm   = warp & 3;
    const int wn   = warp >> 2;
    const int m0   = blockIdx.y * 128;
    const int n0   = blockIdx.x * 128;

    float acc[2][8][4];
#pragma unroll
    for (int mt = 0; mt < 2; mt++)
#pragma unroll
        for (int nt = 0; nt < 8; nt++)
#pragma unroll
            for (int e = 0; e < 4; e++) acc[mt][nt][e] = 0.f;

    for (int k0 = 0; k0 < 1024; k0 += 32) {
#pragma unroll
        for (int i = 0; i < 4; i++) {          // A tile 128x32
            int id = tid + i * 256;
            int r = id >> 3, c4 = id & 7;
            *(float4*)&As[r][c4 * 4] = *(const float4*)&A[(size_t)(m0 + r) * 1024 + k0 + c4 * 4];
        }
#pragma unroll
        for (int i = 0; i < 4; i++) {          // W tile 32x128
            int id = tid + i * 256;
            int kr = id >> 5, nc4 = id & 31;
            float4 w4 = *(const float4*)&W[(size_t)(k0 + kr) * 1024 + n0 + nc4 * 4];
            float* p = &Ws[kr][nc4 * 4];
            ((float2*)p)[0] = make_float2(w4.x, w4.y);
            ((float2*)p)[1] = make_float2(w4.z, w4.w);
        }
        __syncthreads();
#pragma unroll
        for (int ks = 0; ks < 4; ks++) {
            const int kk = ks * 8;
            unsigned af[2][4], bf[8][2];
#pragma unroll
            for (int mt = 0; mt < 2; mt++) {
                int rb = wm * 32 + mt * 16;
                af[mt][0] = f2tf(As[rb + g][kk + tig]);
                af[mt][1] = f2tf(As[rb + 8 + g][kk + tig]);
                af[mt][2] = f2tf(As[rb + g][kk + tig + 4]);
                af[mt][3] = f2tf(As[rb + 8 + g][kk + tig + 4]);
            }
#pragma unroll
            for (int nt = 0; nt < 8; nt++) {
                int nb = wn * 64 + nt * 8;
                bf[nt][0] = f2tf(Ws[kk + tig][nb + g]);
                bf[nt][1] = f2tf(Ws[kk + tig + 4][nb + g]);
            }
#pragma unroll
            for (int mt = 0; mt < 2; mt++)
#pragma unroll
                for (int nt = 0; nt < 8; nt++) mma8(acc[mt][nt], af[mt], bf[nt]);
        }
        __syncthreads();
    }
    // epilogue: scatter to head layout with bias
#pragma unroll
    for (int mt = 0; mt < 2; mt++) {
        int rb = wm * 32 + mt * 16;
#pragma unroll
        for (int nt = 0; nt < 8; nt++) {
            int gn = n0 + wn * 64 + nt * 8 + 2 * tig;
            int h = gn >> 6, d = gn & 63;
            float b0v = bias[gn], b1v = bias[gn + 1];
#pragma unroll
            for (int hh = 0; hh < 2; hh++) {
                int gm = m0 + rb + hh * 8 + g;
                int bb_ = gm >> 11, l = gm & 2047;
                float2 o;
                o.x = acc[mt][nt][hh * 2 + 0] + b0v;
                o.y = acc[mt][nt][hh * 2 + 1] + b1v;
                *(float2*)&dst[(size_t)((bb_ * Hn + h) * Ln + l) * 64 + d] = o;
            }
        }
    }
}

// ---------------------------------------------------------------------------
// Output projection (tf32 mma): out = gather(g_oh) @ Wo + bo
// ---------------------------------------------------------------------------
__global__ __launch_bounds__(256) void out_proj_kernel(
    const float* __restrict__ Wo, const float* __restrict__ bo, float* __restrict__ out)
{
    __shared__ float As[128][40];
    __shared__ float Ws[32][136];

    const int tid  = threadIdx.x;
    const int lane = tid & 31;
    const int warp = tid >> 5;
    const int g    = lane >> 2;
    const int tig  = lane & 3;
    const int wm   = warp & 3;
    const int wn   = warp >> 2;
    const int m0   = blockIdx.y * 128;
    const int n0   = blockIdx.x * 128;

    float acc[2][8][4];
#pragma unroll
    for (int mt = 0; mt < 2; mt++)
#pragma unroll
        for (int nt = 0; nt < 8; nt++)
#pragma unroll
            for (int e = 0; e < 4; e++) acc[mt][nt][e] = 0.f;

    for (int k0 = 0; k0 < 1024; k0 += 32) {
#pragma unroll
        for (int i = 0; i < 4; i++) {          // gather A from head layout
            int id = tid + i * 256;
            int r = id >> 3, c4 = id & 7;
            int gr = m0 + r;
            int bb_ = gr >> 11, l = gr & 2047;
            int kk = k0 + c4 * 4;
            int h = kk >> 6, dv = kk & 63;
            *(float4*)&As[r][c4 * 4] =
                *(const float4*)&g_oh[(size_t)((bb_ * Hn + h) * Ln + l) * 64 + dv];
        }
#pragma unroll
        for (int i = 0; i < 4; i++) {
            int id = tid + i * 256;
            int kr = id >> 5, nc4 = id & 31;
            float4 w4 = *(const float4*)&Wo[(size_t)(k0 + kr) * 1024 + n0 + nc4 * 4];
            float* p = &Ws[kr][nc4 * 4];
            ((float2*)p)[0] = make_float2(w4.x, w4.y);
            ((float2*)p)[1] = make_float2(w4.z, w4.w);
        }
        __syncthreads();
#pragma unroll
        for (int ks = 0; ks < 4; ks++) {
            const int kk = ks * 8;
            unsigned af[2][4], bf[8][2];
#pragma unroll
            for (int mt = 0; mt < 2; mt++) {
                int rb = wm * 32 + mt * 16;
                af[mt][0] = f2tf(As[rb + g][kk + tig]);
                af[mt][1] = f2tf(As[rb + 8 + g][kk + tig]);
                af[mt][2] = f2tf(As[rb + g][kk + tig + 4]);
                af[mt][3] = f2tf(As[rb + 8 + g][kk + tig + 4]);
            }
#pragma unroll
            for (int nt = 0; nt < 8; nt++) {
                int nb = wn * 64 + nt * 8;
                bf[nt][0] = f2tf(Ws[kk + tig][nb + g]);
                bf[nt][1] = f2tf(Ws[kk + tig + 4][nb + g]);
            }
#pragma unroll
            for (int mt = 0; mt < 2; mt++)
#pragma unroll
                for (int nt = 0; nt < 8; nt++) mma8(acc[mt][nt], af[mt], bf[nt]);
        }
        __syncthreads();
    }
#pragma unroll
    for (int mt = 0; mt < 2; mt++) {
        int rb = wm * 32 + mt * 16;
#pragma unroll
        for (int nt = 0; nt < 8; nt++) {
            int gn = n0 + wn * 64 + nt * 8 + 2 * tig;
            float b0v = bo[gn], b1v = bo[gn + 1];
#pragma unroll
            for (int hh = 0; hh < 2; hh++) {
                int gm = m0 + rb + hh * 8 + g;
                float2 o;
                o.x = acc[mt][nt][hh * 2 + 0] + b0v;
                o.y = acc[mt][nt][hh * 2 + 1] + b1v;
                *(float2*)&out[(size_t)gm * 1024 + gn] = o;
            }
        }
    }
}

// ---------------------------------------------------------------------------
// Attention: one CTA per (b, h, 128-row q block). Two passes over j-chunks.
// Pass 1: S = QK^T/8, p = exp(s)*mask, accumulate row sums (registers).
// Pass 2: recompute p, multiply 1/rowsum, write attn, accumulate O = P@V.
// Warp layout for scores: 4m x 2n over 128x128; for PV: 4m x 2n over 128x64.
// ---------------------------------------------------------------------------
#define LDQ 68
#define LDK 68
#define LDV 72
#define LDP 132
#define ATTN_SMEM_FLOATS (128*LDQ + 128*LDK + 128*LDV + 128*LDP + 256 + 128)

__global__ __launch_bounds__(256, 1) void attn_kernel(
    const int* __restrict__ mask, float* __restrict__ attn_out)
{
    extern __shared__ float sm[];
    float* Qs   = sm;
    float* Ks   = Qs + 128 * LDQ;
    float* Vs   = Ks + 128 * LDK;
    float* Ps   = Vs + 128 * LDV;
    float* part = Ps + 128 * LDP;   // [2][128]
    float* invs = part + 256;       // [128]

    const int tid  = threadIdx.x;
    const int lane = tid & 31;
    const int warp = tid >> 5;
    const int g    = lane >> 2;
    const int tig  = lane & 3;
    const int wm   = warp & 3;
    const int wn   = warp >> 2;

    const int q0 = blockIdx.x * 128;
    const int h  = blockIdx.y;
    const int b  = blockIdx.z;
    const int bh = b * Hn + h;
    const float* Qh = g_qh + (size_t)bh * Ln * 64;
    const float* Kh = g_kh + (size_t)bh * Ln * 64;
    const float* Vh = g_vh + (size_t)bh * Ln * 64;
    const int* maskb = mask + (size_t)b * Ln * Ln;

    // load Q block [128][64]
#pragma unroll
    for (int i = 0; i < 8; i++) {
        int id = tid + i * 256;
        int r = id >> 4, c4 = id & 15;
        *(float4*)&Qs[r * LDQ + c4 * 4] = *(const float4*)&Qh[(size_t)(q0 + r) * 64 + c4 * 4];
    }
    __syncthreads();

    // ======================= PASS 1: row sums =======================
    float rsum[2][2] = {{0.f, 0.f}, {0.f, 0.f}};
    for (int jc = 0; jc < 16; jc++) {
        const int j0 = jc * 128;
#pragma unroll
        for (int i = 0; i < 8; i++) {
            int id = tid + i * 256;
            int r = id >> 4, c4 = id & 15;
            *(float4*)&Ks[r * LDK + c4 * 4] = *(const float4*)&Kh[(size_t)(j0 + r) * 64 + c4 * 4];
        }
        __syncthreads();

        float acc[2][8][4];
#pragma unroll
        for (int mt = 0; mt < 2; mt++)
#pragma unroll
            for (int nt = 0; nt < 8; nt++)
#pragma unroll
                for (int e = 0; e < 4; e++) acc[mt][nt][e] = 0.f;
#pragma unroll
        for (int ks = 0; ks < 8; ks++) {
            const int kk = ks * 8;
            unsigned af[2][4], bf[8][2];
#pragma unroll
            for (int mt = 0; mt < 2; mt++) {
                int rb = wm * 32 + mt * 16;
                af[mt][0] = f2tf(Qs[(rb + g) * LDQ + kk + tig]);
                af[mt][1] = f2tf(Qs[(rb + 8 + g) * LDQ + kk + tig]);
                af[mt][2] = f2tf(Qs[(rb + g) * LDQ + kk + tig + 4]);
                af[mt][3] = f2tf(Qs[(rb + 8 + g) * LDQ + kk + tig + 4]);
            }
#pragma unroll
            for (int nt = 0; nt < 8; nt++) {
                int nb = wn * 64 + nt * 8;
                bf[nt][0] = f2tf(Ks[(nb + g) * LDK + kk + tig]);
                bf[nt][1] = f2tf(Ks[(nb + g) * LDK + kk + tig + 4]);
            }
#pragma unroll
            for (int mt = 0; mt < 2; mt++)
#pragma unroll
                for (int nt = 0; nt < 8; nt++) mma8(acc[mt][nt], af[mt], bf[nt]);
        }

#pragma unroll
        for (int mt = 0; mt < 2; mt++) {
            int rb = wm * 32 + mt * 16;
            const int* m0p = maskb + (size_t)(q0 + rb + g) * Ln + j0;
            const int* m1p = maskb + (size_t)(q0 + rb + 8 + g) * Ln + j0;
#pragma unroll
            for (int nt = 0; nt < 8; nt++) {
                int c = wn * 64 + nt * 8 + 2 * tig;
                int2 mA = *(const int2*)(m0p + c);
                int2 mB = *(const int2*)(m1p + c);
                float p0 = mA.x ? __expf(acc[mt][nt][0] * 0.125f) : 0.f;
                float p1 = mA.y ? __expf(acc[mt][nt][1] * 0.125f) : 0.f;
                float p2 = mB.x ? __expf(acc[mt][nt][2] * 0.125f) : 0.f;
                float p3 = mB.y ? __expf(acc[mt][nt][3] * 0.125f) : 0.f;
                rsum[mt][0] += p0 + p1;
                rsum[mt][1] += p2 + p3;
            }
        }
        __syncthreads();
    }

    // reduce row sums
#pragma unroll
    for (int mt = 0; mt < 2; mt++)
#pragma unroll
        for (int hh = 0; hh < 2; hh++) {
            float vv = rsum[mt][hh];
            vv += __shfl_xor_sync(~0u, vv, 1);
            vv += __shfl_xor_sync(~0u, vv, 2);
            if (tig == 0) part[wn * 128 + wm * 32 + mt * 16 + hh * 8 + g] = vv;
        }
    __syncthreads();
    if (tid < 128) invs[tid] = 1.f / (part[tid] + part[128 + tid]);
    __syncthreads();

    // ======================= PASS 2: attn + O =======================
    float oacc[2][4][4];
#pragma unroll
    for (int mt = 0; mt < 2; mt++)
#pragma unroll
        for (int nt = 0; nt < 4; nt++)
#pragma unroll
            for (int e = 0; e < 4; e++) oacc[mt][nt][e] = 0.f;

    float myinv[2][2];
#pragma unroll
    for (int mt = 0; mt < 2; mt++)
#pragma unroll
        for (int hh = 0; hh < 2; hh++)
            myinv[mt][hh] = invs[wm * 32 + mt * 16 + hh * 8 + g];

    for (int jc = 0; jc < 16; jc++) {
        const int j0 = jc * 128;
#pragma unroll
        for (int i = 0; i < 8; i++) {
            int id = tid + i * 256;
            int r = id >> 4, c4 = id & 15;
            *(float4*)&Ks[r * LDK + c4 * 4] = *(const float4*)&Kh[(size_t)(j0 + r) * 64 + c4 * 4];
        }
#pragma unroll
        for (int i = 0; i < 8; i++) {
            int id = tid + i * 256;
            int r = id >> 4, c4 = id & 15;
            *(float4*)&Vs[r * LDV + c4 * 4] = *(const float4*)&Vh[(size_t)(j0 + r) * 64 + c4 * 4];
        }
        __syncthreads();

        float acc[2][8][4];
#pragma unroll
        for (int mt = 0; mt < 2; mt++)
#pragma unroll
            for (int nt = 0; nt < 8; nt++)
#pragma unroll
                for (int e = 0; e < 4; e++) acc[mt][nt][e] = 0.f;
#pragma unroll
        for (int ks = 0; ks < 8; ks++) {
            const int kk = ks * 8;
            unsigned af[2][4], bf[8][2];
#pragma unroll
            for (int mt = 0; mt < 2; mt++) {
                int rb = wm * 32 + mt * 16;
                af[mt][0] = f2tf(Qs[(rb + g) * LDQ + kk + tig]);
                af[mt][1] = f2tf(Qs[(rb + 8 + g) * LDQ + kk + tig]);
                af[mt][2] = f2tf(Qs[(rb + g) * LDQ + kk + tig + 4]);
                af[mt][3] = f2tf(Qs[(rb + 8 + g) * LDQ + kk + tig + 4]);
            }
#pragma unroll
            for (int nt = 0; nt < 8; nt++) {
                int nb = wn * 64 + nt * 8;
                bf[nt][0] = f2tf(Ks[(nb + g) * LDK + kk + tig]);
                bf[nt][1] = f2tf(Ks[(nb + g) * LDK + kk + tig + 4]);
            }
#pragma unroll
            for (int mt = 0; mt < 2; mt++)
#pragma unroll
                for (int nt = 0; nt < 8; nt++) mma8(acc[mt][nt], af[mt], bf[nt]);
        }

        // normalized probabilities -> Ps (smem) + attn (gmem)
#pragma unroll
        for (int mt = 0; mt < 2; mt++) {
            int rb = wm * 32 + mt * 16;
            int r0g = q0 + rb + g;
            int r1g = r0g + 8;
            const int* m0p = maskb + (size_t)r0g * Ln + j0;
            const int* m1p = maskb + (size_t)r1g * Ln + j0;
            float* a0p = attn_out + ((size_t)bh * Ln + r0g) * Ln + j0;
            float* a1p = attn_out + ((size_t)bh * Ln + r1g) * Ln + j0;
#pragma unroll
            for (int nt = 0; nt < 8; nt++) {
                int c = wn * 64 + nt * 8 + 2 * tig;
                int2 mA = *(const int2*)(m0p + c);
                int2 mB = *(const int2*)(m1p + c);
                float p0 = mA.x ? __expf(acc[mt][nt][0] * 0.125f) * myinv[mt][0] : 0.f;
                float p1 = mA.y ? __expf(acc[mt][nt][1] * 0.125f) * myinv[mt][0] : 0.f;
                float p2 = mB.x ? __expf(acc[mt][nt][2] * 0.125f) * myinv[mt][1] : 0.f;
                float p3 = mB.y ? __expf(acc[mt][nt][3] * 0.125f) * myinv[mt][1] : 0.f;
                *(float2*)&Ps[(rb + g) * LDP + c]     = make_float2(p0, p1);
                *(float2*)&Ps[(rb + 8 + g) * LDP + c] = make_float2(p2, p3);
                *(float2*)(a0p + c) = make_float2(p0, p1);
                *(float2*)(a1p + c) = make_float2(p2, p3);
            }
        }
        __syncthreads();

        // O += P @ V   (warp tile 32m x 32n)
#pragma unroll
        for (int ks = 0; ks < 16; ks++) {
            const int kk = ks * 8;
            unsigned af[2][4], bf[4][2];
#pragma unroll
            for (int mt = 0; mt < 2; mt++) {
                int rb = wm * 32 + mt * 16;
                af[mt][0] = f2tf(Ps[(rb + g) * LDP + kk + tig]);
                af[mt][1] = f2tf(Ps[(rb + 8 + g) * LDP + kk + tig]);
                af[mt][2] = f2tf(Ps[(rb + g) * LDP + kk + tig + 4]);
                af[mt][3] = f2tf(Ps[(rb + 8 + g) * LDP + kk + tig + 4]);
            }
#pragma unroll
            for (int nt = 0; nt < 4; nt++) {
                int nb = wn * 32 + nt * 8;
                bf[nt][0] = f2tf(Vs[(kk + tig) * LDV + nb + g]);
                bf[nt][1] = f2tf(Vs[(kk + tig + 4) * LDV + nb + g]);
            }
#pragma unroll
            for (int mt = 0; mt < 2; mt++)
#pragma unroll
                for (int nt = 0; nt < 4; nt++) mma8(oacc[mt][nt], af[mt], bf[nt]);
        }
        __syncthreads();
    }

    // write O block to g_oh
#pragma unroll
    for (int mt = 0; mt < 2; mt++) {
        int rb = wm * 32 + mt * 16;
#pragma unroll
        for (int nt = 0; nt < 4; nt++) {
            int c = wn * 32 + nt * 8 + 2 * tig;
#pragma unroll
            for (int hh = 0; hh < 2; hh++) {
                int r = q0 + rb + hh * 8 + g;
                float2 o;
                o.x = oacc[mt][nt][hh * 2 + 0];
                o.y = oacc[mt][nt][hh * 2 + 1];
                *(float2*)&g_oh[((size_t)bh * Ln + r) * 64 + c] = o;
            }
        }
    }
}

// ---------------------------------------------------------------------------
extern "C" void kernel_launch(void* const* d_in, const int* in_sizes, int n_in,
                              void* d_out, int out_size)
{
    const float* q    = (const float*)d_in[0];
    const float* k    = (const float*)d_in[1];
    const float* v    = (const float*)d_in[2];
    const int*   mask = (const int*)d_in[3];
    const float* Wq   = (const float*)d_in[4];
    const float* bq   = (const float*)d_in[5];
    const float* Wk   = (const float*)d_in[6];
    const float* bk   = (const float*)d_in[7];
    const float* Wv   = (const float*)d_in[8];
    const float* bv   = (const float*)d_in[9];
    const float* Wo   = (const float*)d_in[10];
    const float* bo   = (const float*)d_in[11];

    float* out  = (float*)d_out;                    // [B,L,D]
    float* attn = out + (size_t)BLn * Dn;           // [B,H,L,L]

    proj_qkv_kernel<<<dim3(8, 64, 3), 256>>>(q, k, v, Wq, Wk, Wv, bq, bk, bv);

    int smem_bytes = ATTN_SMEM_FLOATS * (int)sizeof(float);
    cudaFuncSetAttribute(attn_kernel, cudaFuncAttributeMaxDynamicSharedMemorySize, smem_bytes);
    attn_kernel<<<dim3(Ln / 128, Hn, Bn), 256, smem_bytes>>>(mask, attn);

    out_proj_kernel<<<dim3(8, 64), 256>>>(Wo, bo, out);
}

// round 4
// speedup vs baseline: 3.9808x; 1.3904x over previous
#include <cuda_runtime.h>
#include <cuda_fp16.h>

#define Bn 4
#define Ln 2048
#define Dn 1024
#define Hn 16
#define BLn (Bn*Ln)   // 8192
#define BHn (Bn*Hn)   // 64

// packed half inputs / weights / head tensors
__device__ __half g_xh[3][(size_t)BLn*Dn];     // q,k,v in half
__device__ __half g_wt[4][(size_t)Dn*Dn];      // W^T [n][k] in half (q,k,v,o)
__device__ unsigned g_mbits[(size_t)Bn*Ln*64]; // mask bits, 64 words/row
__device__ __half g_qh[(size_t)BHn*Ln*64];
__device__ __half g_kh[(size_t)BHn*Ln*64];
__device__ __half g_vh[(size_t)BHn*Ln*64];
__device__ __half g_vt[(size_t)BHn*64*Ln];     // V transposed [bh][d][l]
__device__ __half g_oh[(size_t)BHn*Ln*64];

// ---------------------------------------------------------------------------
__device__ __forceinline__ void hmma(float d[4], const unsigned a[4], const unsigned b[2]) {
    asm volatile(
        "mma.sync.aligned.m16n8k16.row.col.f32.f16.f16.f32 "
        "{%0,%1,%2,%3}, {%4,%5,%6,%7}, {%8,%9}, {%0,%1,%2,%3};"
        : "+f"(d[0]), "+f"(d[1]), "+f"(d[2]), "+f"(d[3])
        : "r"(a[0]), "r"(a[1]), "r"(a[2]), "r"(a[3]), "r"(b[0]), "r"(b[1]));
}
__device__ __forceinline__ unsigned ldh2(const __half* p) { return *(const unsigned*)p; }

// ---------------------------------------------------------------------------
// pack kernels
// ---------------------------------------------------------------------------
__global__ __launch_bounds__(256) void pack_x_kernel(
    const float* __restrict__ q, const float* __restrict__ k, const float* __restrict__ v)
{
    int z = blockIdx.y;
    const float* src = (z == 0) ? q : (z == 1) ? k : v;
    __half* dst = g_xh[z];
    size_t i = (size_t)blockIdx.x * 256 + threadIdx.x;   // float4 index
    float4 a = ((const float4*)src)[i];
    __half2 h0 = __floats2half2_rn(a.x, a.y);
    __half2 h1 = __floats2half2_rn(a.z, a.w);
    ((__half2*)dst)[2 * i]     = h0;
    ((__half2*)dst)[2 * i + 1] = h1;
}

__global__ void pack_w_kernel(
    const float* __restrict__ Wq, const float* __restrict__ Wk,
    const float* __restrict__ Wv, const float* __restrict__ Wo)
{
    __shared__ float s[32][33];
    int z = blockIdx.z;
    const float* W = (z == 0) ? Wq : (z == 1) ? Wk : (z == 2) ? Wv : Wo;
    __half* dst = g_wt[z];
    int k0 = blockIdx.x * 32, n0 = blockIdx.y * 32;
    int tx = threadIdx.x, ty = threadIdx.y;   // (32, 8)
#pragma unroll
    for (int i = 0; i < 4; i++)
        s[ty + 8 * i][tx] = W[(size_t)(k0 + ty + 8 * i) * 1024 + n0 + tx];
    __syncthreads();
#pragma unroll
    for (int i = 0; i < 4; i++)
        dst[(size_t)(n0 + ty + 8 * i) * 1024 + k0 + tx] = __float2half(s[tx][ty + 8 * i]);
}

__global__ __launch_bounds__(256) void pack_mask_kernel(const int* __restrict__ mask)
{
    size_t i = (size_t)blockIdx.x * 256 + threadIdx.x;
    int m = mask[i];
    unsigned w = __ballot_sync(~0u, m != 0);
    if ((threadIdx.x & 31) == 0) g_mbits[i >> 5] = w;
}

__global__ __launch_bounds__(256) void transpose_v_kernel()
{
    __shared__ __half s[64 * 72];
    int l0 = blockIdx.x * 64;
    int bh = blockIdx.y;
    const __half* src = g_vh + (size_t)bh * Ln * 64;
    __half* dst = g_vt + (size_t)bh * 64 * Ln;
    int tid = threadIdx.x;
    // load 64 rows x 64 halves = 512 uint4
#pragma unroll
    for (int i = 0; i < 2; i++) {
        int id = tid + i * 256;
        int r = id >> 3, c8 = id & 7;
        *(uint4*)&s[r * 72 + c8 * 8] = *(const uint4*)&src[(size_t)(l0 + r) * 64 + c8 * 8];
    }
    __syncthreads();
    // write transposed: 64 d-rows x 64 l-cols = 512 uint4
#pragma unroll
    for (int i = 0; i < 2; i++) {
        int id = tid + i * 256;
        int d = id >> 3, c8 = id & 7;
        __half tmp[8];
#pragma unroll
        for (int j = 0; j < 8; j++) tmp[j] = s[(c8 * 8 + j) * 72 + d];
        *(uint4*)&dst[(size_t)d * Ln + l0 + c8 * 8] = *(uint4*)tmp;
    }
}

// ---------------------------------------------------------------------------
// QKV projection (fp16 mma): C = A @ W + b -> head layout
// ---------------------------------------------------------------------------
__global__ __launch_bounds__(256) void proj_qkv_kernel(
    const float* __restrict__ bq, const float* __restrict__ bk, const float* __restrict__ bv)
{
    const int z = blockIdx.z;
    const __half* A  = g_xh[z];
    const __half* Wt = g_wt[z];
    const float* bias = (z == 0) ? bq : (z == 1) ? bk : bv;
    __half* dst = (z == 0) ? g_qh : (z == 1) ? g_kh : g_vh;

    __shared__ __half As[128 * 40];
    __shared__ __half Ws[128 * 40];

    const int tid  = threadIdx.x;
    const int lane = tid & 31;
    const int warp = tid >> 5;
    const int g    = lane >> 2;
    const int tig  = lane & 3;
    const int wm   = warp & 3;
    const int wn   = warp >> 2;
    const int m0   = blockIdx.y * 128;
    const int n0   = blockIdx.x * 128;

    float acc[2][8][4];
#pragma unroll
    for (int mt = 0; mt < 2; mt++)
#pragma unroll
        for (int nt = 0; nt < 8; nt++)
#pragma unroll
            for (int e = 0; e < 4; e++) acc[mt][nt][e] = 0.f;

    for (int k0 = 0; k0 < 1024; k0 += 32) {
        // 128 rows x 32 halves = 512 uint4 per tile
#pragma unroll
        for (int i = 0; i < 2; i++) {
            int id = tid + i * 256;
            int r = id >> 2, c8 = id & 3;
            *(uint4*)&As[r * 40 + c8 * 8] = *(const uint4*)&A[(size_t)(m0 + r) * 1024 + k0 + c8 * 8];
            *(uint4*)&Ws[r * 40 + c8 * 8] = *(const uint4*)&Wt[(size_t)(n0 + r) * 1024 + k0 + c8 * 8];
        }
        __syncthreads();
#pragma unroll
        for (int ks = 0; ks < 2; ks++) {
            const int kk = ks * 16;
            unsigned af[2][4], bf[8][2];
#pragma unroll
            for (int mt = 0; mt < 2; mt++) {
                int rb = wm * 32 + mt * 16;
                af[mt][0] = ldh2(&As[(rb + g) * 40 + kk + 2 * tig]);
                af[mt][1] = ldh2(&As[(rb + 8 + g) * 40 + kk + 2 * tig]);
                af[mt][2] = ldh2(&As[(rb + g) * 40 + kk + 2 * tig + 8]);
                af[mt][3] = ldh2(&As[(rb + 8 + g) * 40 + kk + 2 * tig + 8]);
            }
#pragma unroll
            for (int nt = 0; nt < 8; nt++) {
                int nb = wn * 64 + nt * 8;
                bf[nt][0] = ldh2(&Ws[(nb + g) * 40 + kk + 2 * tig]);
                bf[nt][1] = ldh2(&Ws[(nb + g) * 40 + kk + 2 * tig + 8]);
            }
#pragma unroll
            for (int mt = 0; mt < 2; mt++)
#pragma unroll
                for (int nt = 0; nt < 8; nt++) hmma(acc[mt][nt], af[mt], bf[nt]);
        }
        __syncthreads();
    }
#pragma unroll
    for (int mt = 0; mt < 2; mt++) {
        int rb = wm * 32 + mt * 16;
#pragma unroll
        for (int nt = 0; nt < 8; nt++) {
            int gn = n0 + wn * 64 + nt * 8 + 2 * tig;
            int h = gn >> 6, d = gn & 63;
            float b0v = bias[gn], b1v = bias[gn + 1];
#pragma unroll
            for (int hh = 0; hh < 2; hh++) {
                int gm = m0 + rb + hh * 8 + g;
                int bb_ = gm >> 11, l = gm & 2047;
                __half2 o = __floats2half2_rn(acc[mt][nt][hh * 2 + 0] + b0v,
                                              acc[mt][nt][hh * 2 + 1] + b1v);
                *(__half2*)&dst[(size_t)((bb_ * Hn + h) * Ln + l) * 64 + d] = o;
            }
        }
    }
}

// ---------------------------------------------------------------------------
// Output projection (fp16 mma): out = gather(g_oh) @ Wo + bo  (fp32 out)
// ---------------------------------------------------------------------------
__global__ __launch_bounds__(256) void out_proj_kernel(
    const float* __restrict__ bo, float* __restrict__ out)
{
    const __half* Wt = g_wt[3];
    __shared__ __half As[128 * 40];
    __shared__ __half Ws[128 * 40];

    const int tid  = threadIdx.x;
    const int lane = tid & 31;
    const int warp = tid >> 5;
    const int g    = lane >> 2;
    const int tig  = lane & 3;
    const int wm   = warp & 3;
    const int wn   = warp >> 2;
    const int m0   = blockIdx.y * 128;
    const int n0   = blockIdx.x * 128;

    float acc[2][8][4];
#pragma unroll
    for (int mt = 0; mt < 2; mt++)
#pragma unroll
        for (int nt = 0; nt < 8; nt++)
#pragma unroll
            for (int e = 0; e < 4; e++) acc[mt][nt][e] = 0.f;

    for (int k0 = 0; k0 < 1024; k0 += 32) {
#pragma unroll
        for (int i = 0; i < 2; i++) {
            int id = tid + i * 256;
            int r = id >> 2, c8 = id & 3;
            int gr = m0 + r;
            int bb_ = gr >> 11, l = gr & 2047;
            int kk = k0 + c8 * 8;
            int h = kk >> 6, dv = kk & 63;
            *(uint4*)&As[r * 40 + c8 * 8] =
                *(const uint4*)&g_oh[(size_t)((bb_ * Hn + h) * Ln + l) * 64 + dv];
            *(uint4*)&Ws[r * 40 + c8 * 8] = *(const uint4*)&Wt[(size_t)(n0 + r) * 1024 + k0 + c8 * 8];
        }
        __syncthreads();
#pragma unroll
        for (int ks = 0; ks < 2; ks++) {
            const int kk = ks * 16;
            unsigned af[2][4], bf[8][2];
#pragma unroll
            for (int mt = 0; mt < 2; mt++) {
                int rb = wm * 32 + mt * 16;
                af[mt][0] = ldh2(&As[(rb + g) * 40 + kk + 2 * tig]);
                af[mt][1] = ldh2(&As[(rb + 8 + g) * 40 + kk + 2 * tig]);
                af[mt][2] = ldh2(&As[(rb + g) * 40 + kk + 2 * tig + 8]);
                af[mt][3] = ldh2(&As[(rb + 8 + g) * 40 + kk + 2 * tig + 8]);
            }
#pragma unroll
            for (int nt = 0; nt < 8; nt++) {
                int nb = wn * 64 + nt * 8;
                bf[nt][0] = ldh2(&Ws[(nb + g) * 40 + kk + 2 * tig]);
                bf[nt][1] = ldh2(&Ws[(nb + g) * 40 + kk + 2 * tig + 8]);
            }
#pragma unroll
            for (int mt = 0; mt < 2; mt++)
#pragma unroll
                for (int nt = 0; nt < 8; nt++) hmma(acc[mt][nt], af[mt], bf[nt]);
        }
        __syncthreads();
    }
#pragma unroll
    for (int mt = 0; mt < 2; mt++) {
        int rb = wm * 32 + mt * 16;
#pragma unroll
        for (int nt = 0; nt < 8; nt++) {
            int gn = n0 + wn * 64 + nt * 8 + 2 * tig;
            float b0v = bo[gn], b1v = bo[gn + 1];
#pragma unroll
            for (int hh = 0; hh < 2; hh++) {
                int gm = m0 + rb + hh * 8 + g;
                float2 o;
                o.x = acc[mt][nt][hh * 2 + 0] + b0v;
                o.y = acc[mt][nt][hh * 2 + 1] + b1v;
                *(float2*)&out[(size_t)gm * 1024 + gn] = o;
            }
        }
    }
}

// ---------------------------------------------------------------------------
// Attention (fp16 mma, two-pass, bit mask)
// smem halves: Qs[128][72], Ks[128][72], Vs[64][136], Ps[128][136]
// ---------------------------------------------------------------------------
#define LDQ 72
#define LDK 72
#define LDV 136
#define LDP 136
#define ATTN_SMEM_BYTES ((256 + 128) * 4 + (128*LDQ + 128*LDK + 64*LDV + 128*LDP) * 2)

__global__ __launch_bounds__(256) void attn_kernel(
    float* __restrict__ attn_out)
{
    extern __shared__ char smraw[];
    float* part = (float*)smraw;            // [2][128]
    float* invs = part + 256;               // [128]
    __half* Qs = (__half*)(invs + 128);
    __half* Ks = Qs + 128 * LDQ;
    __half* Vs = Ks + 128 * LDK;
    __half* Ps = Vs + 64 * LDV;

    const int tid  = threadIdx.x;
    const int lane = tid & 31;
    const int warp = tid >> 5;
    const int g    = lane >> 2;
    const int tig  = lane & 3;
    const int wm   = warp & 3;
    const int wn   = warp >> 2;

    const int q0 = blockIdx.x * 128;
    const int h  = blockIdx.y;
    const int b  = blockIdx.z;
    const int bh = b * Hn + h;
    const __half* Qh = g_qh + (size_t)bh * Ln * 64;
    const __half* Kh = g_kh + (size_t)bh * Ln * 64;
    const __half* Vt = g_vt + (size_t)bh * 64 * Ln;
    const unsigned* mb = g_mbits + (size_t)b * Ln * 64;

    // load Q block: 128 rows x 64 halves = 1024 uint4
#pragma unroll
    for (int i = 0; i < 4; i++) {
        int id = tid + i * 256;
        int r = id >> 3, c8 = id & 7;
        *(uint4*)&Qs[r * LDQ + c8 * 8] = *(const uint4*)&Qh[(size_t)(q0 + r) * 64 + c8 * 8];
    }
    __syncthreads();

    // ======================= PASS 1: row sums =======================
    float rsum[2][2] = {{0.f, 0.f}, {0.f, 0.f}};
    for (int jc = 0; jc < 16; jc++) {
        const int j0 = jc * 128;
#pragma unroll
        for (int i = 0; i < 4; i++) {
            int id = tid + i * 256;
            int r = id >> 3, c8 = id & 7;
            *(uint4*)&Ks[r * LDK + c8 * 8] = *(const uint4*)&Kh[(size_t)(j0 + r) * 64 + c8 * 8];
        }
        __syncthreads();

        float acc[2][8][4];
#pragma unroll
        for (int mt = 0; mt < 2; mt++)
#pragma unroll
            for (int nt = 0; nt < 8; nt++)
#pragma unroll
                for (int e = 0; e < 4; e++) acc[mt][nt][e] = 0.f;
#pragma unroll
        for (int ks = 0; ks < 4; ks++) {
            const int kk = ks * 16;
            unsigned af[2][4], bf[8][2];
#pragma unroll
            for (int mt = 0; mt < 2; mt++) {
                int rb = wm * 32 + mt * 16;
                af[mt][0] = ldh2(&Qs[(rb + g) * LDQ + kk + 2 * tig]);
                af[mt][1] = ldh2(&Qs[(rb + 8 + g) * LDQ + kk + 2 * tig]);
                af[mt][2] = ldh2(&Qs[(rb + g) * LDQ + kk + 2 * tig + 8]);
                af[mt][3] = ldh2(&Qs[(rb + 8 + g) * LDQ + kk + 2 * tig + 8]);
            }
#pragma unroll
            for (int nt = 0; nt < 8; nt++) {
                int nb = wn * 64 + nt * 8;
                bf[nt][0] = ldh2(&Ks[(nb + g) * LDK + kk + 2 * tig]);
                bf[nt][1] = ldh2(&Ks[(nb + g) * LDK + kk + 2 * tig + 8]);
            }
#pragma unroll
            for (int mt = 0; mt < 2; mt++)
#pragma unroll
                for (int nt = 0; nt < 8; nt++) hmma(acc[mt][nt], af[mt], bf[nt]);
        }

#pragma unroll
        for (int mt = 0; mt < 2; mt++) {
            int rb = wm * 32 + mt * 16;
            uint2 w0 = *(const uint2*)&mb[(size_t)(q0 + rb + g) * 64 + jc * 4 + wn * 2];
            uint2 w1 = *(const uint2*)&mb[(size_t)(q0 + rb + 8 + g) * 64 + jc * 4 + wn * 2];
#pragma unroll
            for (int nt = 0; nt < 8; nt++) {
                int cb  = nt * 8 + 2 * tig;
                int bit = cb & 31;
                unsigned m0w = (cb >> 5) ? w0.y : w0.x;
                unsigned m1w = (cb >> 5) ? w1.y : w1.x;
                float p0 = ((m0w >> bit) & 1u)       ? __expf(acc[mt][nt][0] * 0.125f) : 0.f;
                float p1 = ((m0w >> (bit + 1)) & 1u) ? __expf(acc[mt][nt][1] * 0.125f) : 0.f;
                float p2 = ((m1w >> bit) & 1u)       ? __expf(acc[mt][nt][2] * 0.125f) : 0.f;
                float p3 = ((m1w >> (bit + 1)) & 1u) ? __expf(acc[mt][nt][3] * 0.125f) : 0.f;
                rsum[mt][0] += p0 + p1;
                rsum[mt][1] += p2 + p3;
            }
        }
        __syncthreads();
    }

#pragma unroll
    for (int mt = 0; mt < 2; mt++)
#pragma unroll
        for (int hh = 0; hh < 2; hh++) {
            float vv = rsum[mt][hh];
            vv += __shfl_xor_sync(~0u, vv, 1);
            vv += __shfl_xor_sync(~0u, vv, 2);
            if (tig == 0) part[wn * 128 + wm * 32 + mt * 16 + hh * 8 + g] = vv;
        }
    __syncthreads();
    if (tid < 128) invs[tid] = 1.f / (part[tid] + part[128 + tid]);
    __syncthreads();

    // ======================= PASS 2: attn + O =======================
    float oacc[2][4][4];
#pragma unroll
    for (int mt = 0; mt < 2; mt++)
#pragma unroll
        for (int nt = 0; nt < 4; nt++)
#pragma unroll
            for (int e = 0; e < 4; e++) oacc[mt][nt][e] = 0.f;

    float myinv[2][2];
#pragma unroll
    for (int mt = 0; mt < 2; mt++)
#pragma unroll
        for (int hh = 0; hh < 2; hh++)
            myinv[mt][hh] = invs[wm * 32 + mt * 16 + hh * 8 + g];

    for (int jc = 0; jc < 16; jc++) {
        const int j0 = jc * 128;
#pragma unroll
        for (int i = 0; i < 4; i++) {
            int id = tid + i * 256;
            int r = id >> 3, c8 = id & 7;
            *(uint4*)&Ks[r * LDK + c8 * 8] = *(const uint4*)&Kh[(size_t)(j0 + r) * 64 + c8 * 8];
        }
        // V^T tile: 64 d-rows x 128 l-cols = 1024 uint4
#pragma unroll
        for (int i = 0; i < 4; i++) {
            int id = tid + i * 256;
            int d = id >> 4, c8 = id & 15;
            *(uint4*)&Vs[d * LDV + c8 * 8] = *(const uint4*)&Vt[(size_t)d * Ln + j0 + c8 * 8];
        }
        __syncthreads();

        float acc[2][8][4];
#pragma unroll
        for (int mt = 0; mt < 2; mt++)
#pragma unroll
            for (int nt = 0; nt < 8; nt++)
#pragma unroll
                for (int e = 0; e < 4; e++) acc[mt][nt][e] = 0.f;
#pragma unroll
        for (int ks = 0; ks < 4; ks++) {
            const int kk = ks * 16;
            unsigned af[2][4], bf[8][2];
#pragma unroll
            for (int mt = 0; mt < 2; mt++) {
                int rb = wm * 32 + mt * 16;
                af[mt][0] = ldh2(&Qs[(rb + g) * LDQ + kk + 2 * tig]);
                af[mt][1] = ldh2(&Qs[(rb + 8 + g) * LDQ + kk + 2 * tig]);
                af[mt][2] = ldh2(&Qs[(rb + g) * LDQ + kk + 2 * tig + 8]);
                af[mt][3] = ldh2(&Qs[(rb + 8 + g) * LDQ + kk + 2 * tig + 8]);
            }
#pragma unroll
            for (int nt = 0; nt < 8; nt++) {
                int nb = wn * 64 + nt * 8;
                bf[nt][0] = ldh2(&Ks[(nb + g) * LDK + kk + 2 * tig]);
                bf[nt][1] = ldh2(&Ks[(nb + g) * LDK + kk + 2 * tig + 8]);
            }
#pragma unroll
            for (int mt = 0; mt < 2; mt++)
#pragma unroll
                for (int nt = 0; nt < 8; nt++) hmma(acc[mt][nt], af[mt], bf[nt]);
        }

#pragma unroll
        for (int mt = 0; mt < 2; mt++) {
            int rb = wm * 32 + mt * 16;
            int r0g = q0 + rb + g;
            int r1g = r0g + 8;
            uint2 w0 = *(const uint2*)&mb[(size_t)r0g * 64 + jc * 4 + wn * 2];
            uint2 w1 = *(const uint2*)&mb[(size_t)r1g * 64 + jc * 4 + wn * 2];
            float* a0p = attn_out + ((size_t)bh * Ln + r0g) * Ln + j0;
            float* a1p = attn_out + ((size_t)bh * Ln + r1g) * Ln + j0;
#pragma unroll
            for (int nt = 0; nt < 8; nt++) {
                int c   = wn * 64 + nt * 8 + 2 * tig;
                int cb  = nt * 8 + 2 * tig;
                int bit = cb & 31;
                unsigned m0w = (cb >> 5) ? w0.y : w0.x;
                unsigned m1w = (cb >> 5) ? w1.y : w1.x;
                float p0 = ((m0w >> bit) & 1u)       ? __expf(acc[mt][nt][0] * 0.125f) * myinv[mt][0] : 0.f;
                float p1 = ((m0w >> (bit + 1)) & 1u) ? __expf(acc[mt][nt][1] * 0.125f) * myinv[mt][0] : 0.f;
                float p2 = ((m1w >> bit) & 1u)       ? __expf(acc[mt][nt][2] * 0.125f) * myinv[mt][1] : 0.f;
                float p3 = ((m1w >> (bit + 1)) & 1u) ? __expf(acc[mt][nt][3] * 0.125f) * myinv[mt][1] : 0.f;
                *(__half2*)&Ps[(rb + g) * LDP + c]     = __floats2half2_rn(p0, p1);
                *(__half2*)&Ps[(rb + 8 + g) * LDP + c] = __floats2half2_rn(p2, p3);
                *(float2*)(a0p + c) = make_float2(p0, p1);
                *(float2*)(a1p + c) = make_float2(p2, p3);
            }
        }
        __syncthreads();

        // O += P @ V
#pragma unroll
        for (int ks = 0; ks < 8; ks++) {
            const int kk = ks * 16;
            unsigned af[2][4], bf[4][2];
#pragma unroll
            for (int mt = 0; mt < 2; mt++) {
                int rb = wm * 32 + mt * 16;
                af[mt][0] = ldh2(&Ps[(rb + g) * LDP + kk + 2 * tig]);
                af[mt][1] = ldh2(&Ps[(rb + 8 + g) * LDP + kk + 2 * tig]);
                af[mt][2] = ldh2(&Ps[(rb + g) * LDP + kk + 2 * tig + 8]);
                af[mt][3] = ldh2(&Ps[(rb + 8 + g) * LDP + kk + 2 * tig + 8]);
            }
#pragma unroll
            for (int nt = 0; nt < 4; nt++) {
                int nb = wn * 32 + nt * 8;
                bf[nt][0] = ldh2(&Vs[(nb + g) * LDV + kk + 2 * tig]);
                bf[nt][1] = ldh2(&Vs[(nb + g) * LDV + kk + 2 * tig + 8]);
            }
#pragma unroll
            for (int mt = 0; mt < 2; mt++)
#pragma unroll
                for (int nt = 0; nt < 4; nt++) hmma(oacc[mt][nt], af[mt], bf[nt]);
        }
        __syncthreads();
    }

    // write O block (half)
    __half* Oh = g_oh + (size_t)bh * Ln * 64;
#pragma unroll
    for (int mt = 0; mt < 2; mt++) {
        int rb = wm * 32 + mt * 16;
#pragma unroll
        for (int nt = 0; nt < 4; nt++) {
            int c = wn * 32 + nt * 8 + 2 * tig;
#pragma unroll
            for (int hh = 0; hh < 2; hh++) {
                int r = q0 + rb + hh * 8 + g;
                __half2 o = __floats2half2_rn(oacc[mt][nt][hh * 2 + 0],
                                              oacc[mt][nt][hh * 2 + 1]);
                *(__half2*)&Oh[(size_t)r * 64 + c] = o;
            }
        }
    }
}

// ---------------------------------------------------------------------------
extern "C" void kernel_launch(void* const* d_in, const int* in_sizes, int n_in,
                              void* d_out, int out_size)
{
    const float* q    = (const float*)d_in[0];
    const float* k    = (const float*)d_in[1];
    const float* v    = (const float*)d_in[2];
    const int*   mask = (const int*)d_in[3];
    const float* Wq   = (const float*)d_in[4];
    const float* bq   = (const float*)d_in[5];
    const float* Wk   = (const float*)d_in[6];
    const float* bk   = (const float*)d_in[7];
    const float* Wv   = (const float*)d_in[8];
    const float* bv   = (const float*)d_in[9];
    const float* Wo   = (const float*)d_in[10];
    const float* bo   = (const float*)d_in[11];

    float* out  = (float*)d_out;                    // [B,L,D]
    float* attn = out + (size_t)BLn * Dn;           // [B,H,L,L]

    pack_x_kernel<<<dim3((BLn * Dn) / 4 / 256, 3), 256>>>(q, k, v);
    pack_w_kernel<<<dim3(32, 32, 4), dim3(32, 8)>>>(Wq, Wk, Wv, Wo);
    pack_mask_kernel<<<(Bn * Ln * Ln) / 256, 256>>>(mask);

    proj_qkv_kernel<<<dim3(8, 64, 3), 256>>>(bq, bk, bv);
    transpose_v_kernel<<<dim3(Ln / 64, BHn), 256>>>();

    cudaFuncSetAttribute(attn_kernel, cudaFuncAttributeMaxDynamicSharedMemorySize, ATTN_SMEM_BYTES);
    attn_kernel<<<dim3(Ln / 128, Hn, Bn), 256, ATTN_SMEM_BYTES>>>(attn);

    out_proj_kernel<<<dim3(8, 64), 256>>>(bo, out);
}